// round 9
// baseline (speedup 1.0000x reference)
#include <cuda_runtime.h>
#include <cuda_bf16.h>
#include <math.h>

#define BB      32
#define TSEQ    512
#define EPROJ   512
#define DUN     1024
#define ODIMC   10000
#define ATTD    320
#define LLEN    128
#define LP1     129
#define SOSEOS  9999
#define NROWS   (BB*LP1)   // 4128
#define GRID    148

typedef unsigned long long ull;
typedef unsigned int u32;

__device__ __forceinline__ ull pack2(float x){ ull r; asm("mov.b64 %0, {%1, %1};":"=l"(r):"f"(x)); return r; }
__device__ __forceinline__ ull packf2(float x, float y){ ull r; asm("mov.b64 %0, {%1, %2};":"=l"(r):"f"(x),"f"(y)); return r; }
__device__ __forceinline__ void fma2(ull &a, ull x, ull y){ asm("fma.rn.f32x2 %0, %1, %2, %3;":"=l"(a):"l"(x),"l"(y),"l"(a)); }
__device__ __forceinline__ float2 unpack2(ull v){ float2 f; asm("mov.b64 {%0, %1}, %2;":"=f"(f.x),"=f"(f.y):"l"(v)); return f; }
__device__ __forceinline__ float sigmoidf_(float x){ return 1.0f/(1.0f+expf(-x)); }
__device__ __forceinline__ void mma_bf16(float* d, const u32* a, const u32* b){
    asm volatile("mma.sync.aligned.m16n8k16.row.col.f32.bf16.bf16.f32 "
        "{%0,%1,%2,%3},{%4,%5,%6,%7},{%8,%9},{%0,%1,%2,%3};"
        :"+f"(d[0]),"+f"(d[1]),"+f"(d[2]),"+f"(d[3])
        :"r"(a[0]),"r"(a[1]),"r"(a[2]),"r"(a[3]),"r"(b[0]),"r"(b[1]));
}
__device__ __forceinline__ u32 f2_to_bf2(float x, float y){
    u32 lo = (u32)__bfloat16_as_ushort(__float2bfloat16(x));
    u32 hi = (u32)__bfloat16_as_ushort(__float2bfloat16(y));
    return lo | (hi << 16);
}
__device__ __forceinline__ ull bf2_to_f2(u32 v){
    float lo = __bfloat162float(__ushort_as_bfloat16((unsigned short)(v & 0xffffu)));
    float hi = __bfloat162float(__ushort_as_bfloat16((unsigned short)(v >> 16)));
    return packf2(lo, hi);
}

// ---------------- scratch ----------------
__device__ float g_pre_enc[BB*TSEQ*ATTD];
__device__ float g_e[BB*TSEQ];
__device__ float g_attc[BB*EPROJ];
__device__ float g_z0[BB*DUN], g_c0[BB*DUN], g_c1[BB*DUN];
__device__ float g_z1[2][BB*DUN];
__device__ float g_gb0[4096], g_gb1[4096];
__device__ __nv_bfloat16 g_zsb[NROWS*DUN];
__device__ __nv_bfloat16 g_W0i[4096*2560];   // gate-interleaved rows 4*j+g
__device__ __nv_bfloat16 g_W1i[4096*2048];
__device__ __nv_bfloat16 g_Wo[(size_t)ODIMC*DUN];
__device__ __nv_bfloat16 g_Wd[ATTD*DUN];
__device__ float g_logits[(size_t)NROWS*ODIMC];
__device__ float g_rownll[NROWS];
__device__ int   g_rowhit[NROWS];
__device__ unsigned g_cnt;
__device__ volatile unsigned g_genv;

__global__ void init_all(const float* bih0, const float* bhh0,
                         const float* bih1, const float* bhh1){
    int i = blockIdx.x*blockDim.x + threadIdx.x;
    if (i < BB*DUN){ g_z0[i]=0.f; g_c0[i]=0.f; g_c1[i]=0.f; g_z1[0][i]=0.f; g_z1[1][i]=0.f; }
    if (i < 4096){
        int j = i >> 2, g = i & 3, old = g*1024 + j;
        g_gb0[i] = bih0[old] + bhh0[old];
        g_gb1[i] = bih1[old] + bhh1[old];
    }
    if (i == 0){ g_cnt = 0u; g_genv = 0u; }
}

// interleaved bf16 conversion: dst row (4*j+g) col k  <-  gate row g*1024+j of [Wih | Whh]
__global__ void convi(const float* __restrict__ a, const float* __restrict__ b,
                      __nv_bfloat16* __restrict__ dst, int K, int K1)
{
    int K2 = K - K1;
    size_t total = (size_t)4096*K;
    for (size_t i = (size_t)blockIdx.x*blockDim.x + threadIdx.x; i < total;
         i += (size_t)gridDim.x*blockDim.x){
        size_t r = i / K; int k = (int)(i - r*K);
        int j = (int)(r >> 2), g = (int)(r & 3);
        size_t old = (size_t)g*1024 + j;
        float v = (k < K1) ? a[old*K1 + k] : b[old*K2 + (k - K1)];
        dst[i] = __float2bfloat16(v);
    }
}

__global__ void convcat(const float* __restrict__ a, __nv_bfloat16* __restrict__ dst, size_t total)
{
    for (size_t i = (size_t)blockIdx.x*blockDim.x + threadIdx.x; i < total;
         i += (size_t)gridDim.x*blockDim.x)
        dst[i] = __float2bfloat16(a[i]);
}

// ---------------- fp32 GEMM for pre_enc: C = tanh(A @ W^T + bias) ----------------
__global__ void sgemm_nt(const float* __restrict__ A, const float* __restrict__ W,
                         const float* __restrict__ bias, float* __restrict__ C,
                         int M, int N, int K, int act)
{
    __shared__ __align__(16) float As[16][68];
    __shared__ __align__(16) float Ws[16][68];
    int bm = blockIdx.x * 64, bn = blockIdx.y * 64;
    int tx = threadIdx.x & 15, ty = threadIdx.x >> 4;
    ull acc[4][2] = {{0ull,0ull},{0ull,0ull},{0ull,0ull},{0ull,0ull}};
    for (int k0 = 0; k0 < K; k0 += 16){
        #pragma unroll
        for (int j=0;j<4;j++){
            int i = threadIdx.x + j*256;
            int m = i >> 4, k = i & 15;
            int gm = bm + m;
            As[k][m] = (gm < M) ? A[(size_t)gm*K + k0 + k] : 0.f;
            int gn = bn + m;
            Ws[k][m] = (gn < N) ? W[(size_t)gn*K + k0 + k] : 0.f;
        }
        __syncthreads();
        #pragma unroll
        for (int k=0;k<16;k++){
            float4 a4 = *(const float4*)&As[k][ty*4];
            ulonglong2 w2 = *(const ulonglong2*)&Ws[k][tx*4];
            ull a;
            a = pack2(a4.x); fma2(acc[0][0],a,w2.x); fma2(acc[0][1],a,w2.y);
            a = pack2(a4.y); fma2(acc[1][0],a,w2.x); fma2(acc[1][1],a,w2.y);
            a = pack2(a4.z); fma2(acc[2][0],a,w2.x); fma2(acc[2][1],a,w2.y);
            a = pack2(a4.w); fma2(acc[3][0],a,w2.x); fma2(acc[3][1],a,w2.y);
        }
        __syncthreads();
    }
    #pragma unroll
    for (int i=0;i<4;i++){
        int m = bm + ty*4 + i;
        if (m >= M) continue;
        #pragma unroll
        for (int jp=0;jp<2;jp++){
            float2 v = unpack2(acc[i][jp]);
            int n = bn + tx*4 + jp*2;
            if (n < N){   float r = v.x + (bias?bias[n]:0.f);   if(act) r=tanhf(r); C[(size_t)m*N+n]   = r; }
            if (n+1 < N){ float r = v.y + (bias?bias[n+1]:0.f); if(act) r=tanhf(r); C[(size_t)m*N+n+1] = r; }
        }
    }
}

// ---------------- grid barrier ----------------
__device__ __forceinline__ void gsync(unsigned target){
    __syncthreads();
    if (threadIdx.x == 0){
        __threadfence();
        unsigned arr = atomicAdd(&g_cnt, 1u);
        if (arr == GRID-1){
            g_cnt = 0u;
            __threadfence();
            g_genv = target;
        } else {
            while (g_genv < target) { __nanosleep(32); }
        }
    }
    __syncthreads();
    __threadfence();   // gpu-scope: invalidate L1D so cross-CTA data is fresh
}

// one 512-K chunk of bf16 MMA: acc[2][4] covers rows 0..31 (b), 8 cols for this warp
__device__ __forceinline__ void mma_chunk(float acc[2][4],
        const __nv_bfloat16* __restrict__ Wl,
        const __nv_bfloat16 (*A_s)[520], int gid, int tg)
{
    const __nv_bfloat16* a0 = &A_s[gid][2*tg];
    const __nv_bfloat16* a1 = &A_s[gid+8][2*tg];
    const __nv_bfloat16* a2 = &A_s[gid+16][2*tg];
    const __nv_bfloat16* a3 = &A_s[gid+24][2*tg];
    #pragma unroll 4
    for (int kk = 0; kk < 512; kk += 16){
        u32 a[2][4], bf[2];
        a[0][0]=*(const u32*)(a0+kk);   a[0][1]=*(const u32*)(a1+kk);
        a[0][2]=*(const u32*)(a0+kk+8); a[0][3]=*(const u32*)(a1+kk+8);
        a[1][0]=*(const u32*)(a2+kk);   a[1][1]=*(const u32*)(a3+kk);
        a[1][2]=*(const u32*)(a2+kk+8); a[1][3]=*(const u32*)(a3+kk+8);
        bf[0]=*(const u32*)(Wl+kk); bf[1]=*(const u32*)(Wl+kk+8);
        mma_bf16(acc[0], a[0], bf);
        mma_bf16(acc[1], a[1], bf);
    }
}

// ---------------- persistent decoder ----------------
__global__ void __launch_bounds__(256, 1)
decoder_loop(const float* __restrict__ hs, const int* __restrict__ hlens,
             const int* __restrict__ ys, const float* __restrict__ embed)
{
    __shared__ __align__(16) float z_s[DUN];
    __shared__ __align__(16) float dec_s[ATTD];
    __shared__ __align__(16) float w_s[TSEQ];
    __shared__ float red_s[12];
    __shared__ __align__(16) float4 pvec[256];
    __shared__ __align__(16) __nv_bfloat16 A_s[32][520];
    __shared__ int tok_s[32];

    int cta = blockIdx.x, tid = threadIdx.x;
    int warp = tid >> 5, lane = tid & 31;
    int gid = lane >> 2, tg = lane & 3;
    bool isG = (cta >= 32 && cta < 96);
    int n0 = (cta - 32) * 64;
    int w8 = n0 + warp*8;           // this warp's column base (gates CTAs)
    int wcol = w8 + 2*tg;           // acc column
    int jj = wcol >> 2;             // cell index
    unsigned bt = 0;

    for (int t = 0; t <= LP1; t++){
        // ================= P1 : scores(t)  ||  gates1+cell1(t-1) =================
        if (cta < 32 && t < LP1){
            int b = cta;
            ((float4*)z_s)[tid] = ((const float4*)(g_z0 + b*DUN))[tid];
            __syncthreads();
            for (int a = warp; a < ATTD; a += 8){
                const __nv_bfloat16* wr = g_Wd + (size_t)a*DUN;
                ull acc = 0ull;
                #pragma unroll
                for (int i2=0;i2<16;i2++){
                    int k = (lane<<1) + (i2<<6);
                    fma2(acc, bf2_to_f2(*(const u32*)(wr + k)), *(const ull*)(z_s + k));
                }
                float2 p = unpack2(acc);
                float v = p.x + p.y;
                #pragma unroll
                for (int o=16;o;o>>=1) v += __shfl_xor_sync(0xffffffffu, v, o);
                if (lane==0) dec_s[a] = tanhf(v);
            }
            __syncthreads();
            int hlen = hlens[b];
            #pragma unroll
            for (int h=0; h<2; h++){
                int tt = tid + h*256;
                const float* pr = g_pre_enc + ((size_t)(b*TSEQ) + tt)*ATTD;
                ull c0=0ull, c1=0ull;
                #pragma unroll
                for (int a=0; a<ATTD; a+=4){
                    fma2(c0, *(const ull*)(pr+a),   *(const ull*)(dec_s+a));
                    fma2(c1, *(const ull*)(pr+a+2), *(const ull*)(dec_s+a+2));
                }
                float2 p0 = unpack2(c0), p1 = unpack2(c1);
                float e = (p0.x+p0.y)+(p1.x+p1.y);
                g_e[b*TSEQ + tt] = (tt < hlen) ? 2.0f*e : -1e30f;
            }
        } else if (isG && t >= 1){
            const float* z1rd = g_z1[t & 1];
            float* z1wr = g_z1[(t+1) & 1];
            float acc1[2][4] = {{0.f,0.f,0.f,0.f},{0.f,0.f,0.f,0.f}};
            for (int ch = 0; ch < 4; ch++){
                int K0 = ch*512;
                for (int i = tid; i < 32*256; i += 256){
                    int mm = i >> 8, kp = (i & 255)*2, kg = K0 + kp;
                    float2 v = (kg < 1024) ? *(const float2*)(g_z0 + mm*DUN + kg)
                                           : *(const float2*)(z1rd + mm*DUN + (kg-1024));
                    *(u32*)&A_s[mm][kp] = f2_to_bf2(v.x, v.y);
                }
                __syncthreads();
                mma_chunk(acc1, g_W1i + (size_t)(w8+gid)*2048 + K0 + 2*tg, A_s, gid, tg);
                __syncthreads();
            }
            float b0g = g_gb1[wcol], b1g = g_gb1[wcol+1];
            #pragma unroll
            for (int mt=0; mt<2; mt++){
                float x0=acc1[mt][0]+b0g, x1=acc1[mt][1]+b1g;
                float y0=acc1[mt][2]+b0g, y1=acc1[mt][3]+b1g;
                float px0=__shfl_xor_sync(0xffffffffu,x0,1);
                float px1=__shfl_xor_sync(0xffffffffu,x1,1);
                float py0=__shfl_xor_sync(0xffffffffu,y0,1);
                float py1=__shfl_xor_sync(0xffffffffu,y1,1);
                if (!(tg & 1)){
                    int r = mt*16 + gid;
                    {
                        int idx = r*DUN + jj;
                        float cn = sigmoidf_(x1)*g_c1[idx] + sigmoidf_(x0)*tanhf(px0);
                        float zn = sigmoidf_(px1)*tanhf(cn);
                        g_c1[idx]=cn; z1wr[idx]=zn;
                        g_zsb[((size_t)r*LP1 + (t-1))*DUN + jj] = __float2bfloat16(zn);
                    }
                    {
                        int idx = (r+8)*DUN + jj;
                        float cn = sigmoidf_(y1)*g_c1[idx] + sigmoidf_(y0)*tanhf(py0);
                        float zn = sigmoidf_(py1)*tanhf(cn);
                        g_c1[idx]=cn; z1wr[idx]=zn;
                        g_zsb[((size_t)(r+8)*LP1 + (t-1))*DUN + jj] = __float2bfloat16(zn);
                    }
                }
            }
        }
        gsync(++bt);

        // ================= P2 : attc(t)  ||  gates0 chunks {0,1,3,4} =================
        float acc0[2][4] = {{0.f,0.f,0.f,0.f},{0.f,0.f,0.f,0.f}};
        if (cta < 32 && t < LP1){
            int b = cta;
            float e0 = g_e[b*TSEQ + tid];
            float e1 = g_e[b*TSEQ + 256 + tid];
            float lm = fmaxf(e0, e1);
            #pragma unroll
            for (int o=16;o;o>>=1) lm = fmaxf(lm, __shfl_xor_sync(0xffffffffu, lm, o));
            if (lane==0) red_s[warp] = lm;
            __syncthreads();
            if (tid==0){ float mm=red_s[0]; for (int w2=1;w2<8;w2++) mm=fmaxf(mm,red_s[w2]); red_s[8]=mm; }
            __syncthreads();
            float m = red_s[8];
            float p0 = expf(e0 - m), p1 = expf(e1 - m);
            w_s[tid] = p0; w_s[tid+256] = p1;
            float ps = p0 + p1;
            #pragma unroll
            for (int o=16;o;o>>=1) ps += __shfl_xor_sync(0xffffffffu, ps, o);
            if (lane==0) red_s[warp] = ps;
            __syncthreads();
            if (tid==0){ float s=0.f; for (int w2=0;w2<8;w2++) s+=red_s[w2]; red_s[9]=1.0f/s; }
            __syncthreads();
            float inv = red_s[9];
            int hlen = hlens[b];
            int d4 = tid & 127, tp = tid >> 7;
            const float4* hb = (const float4*)hs + ((size_t)(b*TSEQ))*128 + d4;
            float4 acc = make_float4(0.f,0.f,0.f,0.f);
            for (int tt = tp; tt < hlen; tt += 2){
                float wv = w_s[tt];
                float4 h4 = hb[(size_t)tt*128];
                acc.x += wv*h4.x; acc.y += wv*h4.y; acc.z += wv*h4.z; acc.w += wv*h4.w;
            }
            pvec[tid] = acc;
            __syncthreads();
            if (tp == 0){
                float4 r = pvec[d4], q = pvec[128 + d4];
                r.x = (r.x + q.x)*inv; r.y = (r.y + q.y)*inv;
                r.z = (r.z + q.z)*inv; r.w = (r.w + q.w)*inv;
                ((float4*)(g_attc + b*EPROJ))[d4] = r;
            }
        } else if (isG && t < LP1){
            if (tid < 32) tok_s[tid] = (t==0) ? SOSEOS : ys[tid*LLEN + (t-1)];
            __syncthreads();
            const int chs[4] = {0,1,3,4};
            #pragma unroll
            for (int ci=0; ci<4; ci++){
                int K0 = chs[ci]*512;
                for (int i = tid; i < 32*256; i += 256){
                    int mm = i >> 8, kp = (i & 255)*2, kg = K0 + kp;
                    float2 v = (kg < 1024) ? *(const float2*)(embed + (size_t)tok_s[mm]*DUN + kg)
                                           : *(const float2*)(g_z0 + mm*DUN + (kg-1536));
                    *(u32*)&A_s[mm][kp] = f2_to_bf2(v.x, v.y);
                }
                __syncthreads();
                mma_chunk(acc0, g_W0i + (size_t)(w8+gid)*2560 + K0 + 2*tg, A_s, gid, tg);
                __syncthreads();
            }
        }
        gsync(++bt);

        // ================= P3 : gates0 attc-chunk + cell0 =================
        if (isG && t < LP1){
            for (int i = tid; i < 32*256; i += 256){
                int mm = i >> 8, kp = (i & 255)*2;
                float2 v = *(const float2*)(g_attc + mm*EPROJ + kp);
                *(u32*)&A_s[mm][kp] = f2_to_bf2(v.x, v.y);
            }
            __syncthreads();
            mma_chunk(acc0, g_W0i + (size_t)(w8+gid)*2560 + 1024 + 2*tg, A_s, gid, tg);

            float b0g = g_gb0[wcol], b1g = g_gb0[wcol+1];
            #pragma unroll
            for (int mt=0; mt<2; mt++){
                float x0=acc0[mt][0]+b0g, x1=acc0[mt][1]+b1g;
                float y0=acc0[mt][2]+b0g, y1=acc0[mt][3]+b1g;
                float px0=__shfl_xor_sync(0xffffffffu,x0,1);
                float px1=__shfl_xor_sync(0xffffffffu,x1,1);
                float py0=__shfl_xor_sync(0xffffffffu,y0,1);
                float py1=__shfl_xor_sync(0xffffffffu,y1,1);
                if (!(tg & 1)){
                    int r = mt*16 + gid;
                    {
                        int idx = r*DUN + jj;
                        float cn = sigmoidf_(x1)*g_c0[idx] + sigmoidf_(x0)*tanhf(px0);
                        float zn = sigmoidf_(px1)*tanhf(cn);
                        g_c0[idx]=cn; g_z0[idx]=zn;
                    }
                    {
                        int idx = (r+8)*DUN + jj;
                        float cn = sigmoidf_(y1)*g_c0[idx] + sigmoidf_(y0)*tanhf(py0);
                        float zn = sigmoidf_(py1)*tanhf(cn);
                        g_c0[idx]=cn; g_z0[idx]=zn;
                    }
                }
            }
        }
        gsync(++bt);
    }
}

// ---------------- bf16 MMA logits: C[4128,10000] = zsb @ Wo^T + bout ----------------
__global__ void logits_mma(const __nv_bfloat16* __restrict__ A, const __nv_bfloat16* __restrict__ Wo,
                           const float* __restrict__ bias, float* __restrict__ Cout)
{
    int bm = blockIdx.x*128, bn = blockIdx.y*128;
    int tid = threadIdx.x, w = tid >> 5, l = tid & 31, gid = l >> 2, tg = l & 3;
    int moff = (w & 3) * 32, noff = (w >> 2) * 64;

    float acc[2][8][4];
    #pragma unroll
    for (int i=0;i<2;i++)
        #pragma unroll
        for (int j=0;j<8;j++)
            #pragma unroll
            for (int q=0;q<4;q++) acc[i][j][q]=0.f;

    int mr[2][2];
    #pragma unroll
    for (int mt=0; mt<2; mt++){
        int r0 = bm + moff + mt*16 + gid, r1 = r0 + 8;
        mr[mt][0] = (r0 < NROWS) ? r0 : (NROWS-1);
        mr[mt][1] = (r1 < NROWS) ? r1 : (NROWS-1);
    }
    int nr[8];
    #pragma unroll
    for (int nt=0; nt<8; nt++){
        int n = bn + noff + nt*8 + gid;
        nr[nt] = (n < ODIMC) ? n : (ODIMC-1);
    }

    for (int kk = 0; kk < DUN; kk += 16){
        u32 a[2][4];
        #pragma unroll
        for (int mt=0; mt<2; mt++){
            const __nv_bfloat16* p0 = A + (size_t)mr[mt][0]*DUN + kk + 2*tg;
            const __nv_bfloat16* p1 = A + (size_t)mr[mt][1]*DUN + kk + 2*tg;
            a[mt][0] = *(const u32*)p0;
            a[mt][1] = *(const u32*)p1;
            a[mt][2] = *(const u32*)(p0 + 8);
            a[mt][3] = *(const u32*)(p1 + 8);
        }
        #pragma unroll
        for (int nt=0; nt<8; nt++){
            const __nv_bfloat16* wp = Wo + (size_t)nr[nt]*DUN + kk + 2*tg;
            u32 bf[2];
            bf[0] = *(const u32*)wp;
            bf[1] = *(const u32*)(wp + 8);
            mma_bf16(acc[0][nt], a[0], bf);
            mma_bf16(acc[1][nt], a[1], bf);
        }
    }

    #pragma unroll
    for (int mt=0; mt<2; mt++){
        #pragma unroll
        for (int nt=0; nt<8; nt++){
            int row0 = bm + moff + mt*16 + gid;
            int col  = bn + noff + nt*8 + 2*tg;
            if (col < ODIMC){
                float b0 = bias[col], b1 = bias[col+1];
                if (row0 < NROWS){
                    float2 v = make_float2(acc[mt][nt][0] + b0, acc[mt][nt][1] + b1);
                    *(float2*)&Cout[(size_t)row0*ODIMC + col] = v;
                }
                if (row0 + 8 < NROWS){
                    float2 v = make_float2(acc[mt][nt][2] + b0, acc[mt][nt][3] + b1);
                    *(float2*)&Cout[(size_t)(row0+8)*ODIMC + col] = v;
                }
            }
        }
    }
}

// ---------------- per-row logsumexp / argmax / nll ----------------
__global__ void rowloss(const float* __restrict__ logits, const int* __restrict__ ys,
                        float* __restrict__ rownll, int* __restrict__ rowhit)
{
    int r = blockIdx.x, tid = threadIdx.x;
    const float* row = logits + (size_t)r*ODIMC;
    __shared__ float sv[256]; __shared__ int si[256]; __shared__ double sd[256];
    float vmax = -INFINITY; int vidx = ODIMC;
    for (int i=tid;i<ODIMC;i+=256){ float v=row[i]; if (v>vmax){ vmax=v; vidx=i; } }
    sv[tid]=vmax; si[tid]=vidx; __syncthreads();
    for (int s=128;s;s>>=1){
        if (tid<s){
            float v2=sv[tid+s]; int i2=si[tid+s];
            if (v2>sv[tid] || (v2==sv[tid] && i2<si[tid])){ sv[tid]=v2; si[tid]=i2; }
        }
        __syncthreads();
    }
    float m = sv[0]; int amax = si[0];
    double ps = 0.0;
    for (int i=tid;i<ODIMC;i+=256) ps += (double)expf(row[i]-m);
    sd[tid]=ps; __syncthreads();
    for (int s=128;s;s>>=1){ if (tid<s) sd[tid]+=sd[tid+s]; __syncthreads(); }
    if (tid==0){
        int b = r / LP1, ll = r % LP1;
        int tgt = (ll < LLEN) ? ys[b*LLEN + ll] : SOSEOS;
        double lse = (double)m + log(sd[0]);
        rownll[r] = (float)(lse - (double)row[tgt]);
        rowhit[r] = (amax == tgt) ? 1 : 0;
    }
}

__global__ void finalize(const float* __restrict__ rownll, const int* __restrict__ rowhit,
                         float* __restrict__ out, int out_size)
{
    __shared__ double sd[256]; __shared__ int sh[256];
    int tid = threadIdx.x;
    double s = 0.0; int h = 0;
    for (int i=tid;i<NROWS;i+=256){ s += (double)rownll[i]; h += rowhit[i]; }
    sd[tid]=s; sh[tid]=h; __syncthreads();
    for (int st=128;st;st>>=1){ if (tid<st){ sd[tid]+=sd[tid+st]; sh[tid]+=sh[tid+st]; } __syncthreads(); }
    if (tid==0){
        double loss = sd[0]/(double)NROWS * (double)LLEN;
        double acc  = (double)sh[0]/(double)NROWS;
        double ppl  = exp(loss/(double)BB);
        if (out_size>0) out[0]=(float)loss;
        if (out_size>1) out[1]=(float)acc;
        if (out_size>2) out[2]=(float)ppl;
    }
    for (int i=3+tid;i<out_size;i+=256) out[i]=0.f;
}

// ---------------- launcher ----------------
static void* symaddr(const void* sym){ void* p=nullptr; cudaGetSymbolAddress(&p, sym); return p; }

extern "C" void kernel_launch(void* const* d_in, const int* in_sizes, int n_in,
                              void* d_out, int out_size)
{
    const float* hs    = (const float*)d_in[0];
    const int*   hlens = (const int*)  d_in[1];
    const int*   ys    = (const int*)  d_in[2];
    const float* embed = (const float*)d_in[3];
    const float* Wenc  = (const float*)d_in[4];
    const float* benc  = (const float*)d_in[5];
    const float* Wdec  = (const float*)d_in[6];
    const float* Wih0  = (const float*)d_in[7];
    const float* Whh0  = (const float*)d_in[8];
    const float* bih0  = (const float*)d_in[9];
    const float* bhh0  = (const float*)d_in[10];
    const float* Wih1  = (const float*)d_in[11];
    const float* Whh1  = (const float*)d_in[12];
    const float* bih1  = (const float*)d_in[13];
    const float* bhh1  = (const float*)d_in[14];
    const float* Wout  = (const float*)d_in[15];
    const float* bout  = (const float*)d_in[16];
    float* out = (float*)d_out;

    float* pre_enc = (float*)symaddr(g_pre_enc);
    __nv_bfloat16* zsb = (__nv_bfloat16*)symaddr(g_zsb);
    __nv_bfloat16* W0i = (__nv_bfloat16*)symaddr(g_W0i);
    __nv_bfloat16* W1i = (__nv_bfloat16*)symaddr(g_W1i);
    __nv_bfloat16* Wob = (__nv_bfloat16*)symaddr(g_Wo);
    __nv_bfloat16* Wdb = (__nv_bfloat16*)symaddr(g_Wd);
    float* logits  = (float*)symaddr(g_logits);
    float* rownll  = (float*)symaddr(g_rownll);
    int*   rowhit  = (int*)  symaddr(g_rowhit);

    init_all<<<128,256>>>(bih0, bhh0, bih1, bhh1);

    convi<<<1024,256>>>(Wih0, Whh0, W0i, 2560, 1536);
    convi<<<1024,256>>>(Wih1, Whh1, W1i, 2048, 1024);
    convcat<<<1024,256>>>(Wout, Wob, (size_t)ODIMC*DUN);
    convcat<<<256,256>>>(Wdec, Wdb, (size_t)ATTD*DUN);

    // pre_enc = tanh(hs @ Wenc^T + benc):  [16384,320]
    sgemm_nt<<<dim3(256,5),256>>>(hs, Wenc, benc, pre_enc, BB*TSEQ, ATTD, EPROJ, 1);

    // entire recurrence in one persistent kernel
    decoder_loop<<<GRID,256>>>(hs, hlens, ys, embed);

    // logits = zsb @ Wo^T + bout
    logits_mma<<<dim3(33,79),256>>>(zsb, Wob, bout, logits);

    rowloss<<<NROWS,256>>>(logits, ys, rownll, rowhit);
    finalize<<<1,256>>>(rownll, rowhit, out, out_size);
}